// round 14
// baseline (speedup 1.0000x reference)
#include <cuda_runtime.h>
#include <cuda_bf16.h>
#include <cstdint>

#define C_  512
#define Hh  24
#define Ww  24
#define HW  576
#define NH  8
#define HD  64
#define PW  30
#define PP  900
#define KP  960
#define SEW 964            /* sE row stride: 4 mod 32 -> conflict-free frag reads */
#define QT_ 16             /* query tile (16 -> 98KB smem -> 2 CTAs/SM) */

typedef unsigned long long ull;

// Scratch (device globals: allocation-free)
__device__ float g_Xp[C_ * KP];   // reflect-padded x, keys padded to 960 (zeros)
__device__ float g_QT[HW * C_];   // Q transposed: [p][o]
__device__ float g_KT[KP * C_];   // K transposed: [pp][o]
__device__ float g_V [C_ * KP];   // V: [o][pp]

// ---- tf32 helpers (attention) ----
__device__ __forceinline__ uint32_t f2tf(float f) {
    uint32_t r; asm("cvt.rna.tf32.f32 %0, %1;" : "=r"(r) : "f"(f)); return r;
}
__device__ __forceinline__ void mma_tf32(float* c, const uint32_t* a, const uint32_t* b) {
    asm("mma.sync.aligned.m16n8k8.row.col.f32.tf32.tf32.f32 "
        "{%0,%1,%2,%3}, {%4,%5,%6,%7}, {%8,%9}, {%0,%1,%2,%3};"
        : "+f"(c[0]), "+f"(c[1]), "+f"(c[2]), "+f"(c[3])
        : "r"(a[0]), "r"(a[1]), "r"(a[2]), "r"(a[3]), "r"(b[0]), "r"(b[1]));
}

// ---- bf16 helpers (gemm) ----
__device__ __forceinline__ uint32_t pkbf(float lo, float hi) {
    __nv_bfloat162 h = __floats2bfloat162_rn(lo, hi);
    return *(uint32_t*)&h;
}
__device__ __forceinline__ void mma_bf16(float* c, const uint32_t* a, const uint32_t* b) {
    asm("mma.sync.aligned.m16n8k16.row.col.f32.bf16.bf16.f32 "
        "{%0,%1,%2,%3}, {%4,%5,%6,%7}, {%8,%9}, {%0,%1,%2,%3};"
        : "+f"(c[0]), "+f"(c[1]), "+f"(c[2]), "+f"(c[3])
        : "r"(a[0]), "r"(a[1]), "r"(a[2]), "r"(a[3]), "r"(b[0]), "r"(b[1]));
}

// ---------------------------------------------------------------------------
// Kernel 1: reflect-pad gather.
// ---------------------------------------------------------------------------
__global__ void pad_kernel(const float* __restrict__ x) {
    int idx = blockIdx.x * 256 + threadIdx.x;
    if (idx >= C_ * KP) return;
    int c = idx / KP, pp = idx - c * KP;
    float v = 0.f;
    if (pp < PP) {
        int pr = pp / PW, pc = pp - pr * PW;
        int r = pr - 3; r = (r < 0) ? -r : ((r >= Hh) ? 2 * Hh - 2 - r : r);
        int cl = pc - 3; cl = (cl < 0) ? -cl : ((cl >= Ww) ? 2 * Ww - 2 - cl : cl);
        v = x[c * HW + r * Ww + cl];
    }
    g_Xp[idx] = v;
}

// ---------------------------------------------------------------------------
// Kernel 2: three conv1x1 GEMMs via mma.sync BF16 m16n8k16 (R13 verbatim).
// ---------------------------------------------------------------------------
__global__ void __launch_bounds__(128) gemm_all_kernel(
    const float* __restrict__ Wq, const float* __restrict__ bq,
    const float* __restrict__ Wk, const float* __restrict__ bk,
    const float* __restrict__ Wv, const float* __restrict__ bv,
    const float* __restrict__ x)
{
    __shared__ uint32_t smu[4736];
    uint32_t* sA[2] = { smu,        smu + 1280 };   // [o=64][k2], stride 20
    uint32_t* sB[2] = { smu + 2560, smu + 3648 };   // [k2=16][n], stride 68

    int bid = blockIdx.x;
    const float *Wm, *bias, *X; float* Cout; int N, transp, nt, ot;
    if (bid < 72)       { nt = bid % 9;      ot = bid / 9;       Wm = Wq; bias = bq; X = x;    Cout = g_QT; N = HW; transp = 1; }
    else if (bid < 192) { int b = bid - 72;  nt = b % 15; ot = b / 15; Wm = Wk; bias = bk; X = g_Xp; Cout = g_KT; N = KP; transp = 1; }
    else                { int b = bid - 192; nt = b % 15; ot = b / 15; Wm = Wv; bias = bv; X = g_Xp; Cout = g_V;  N = KP; transp = 0; }
    int nB = nt * 64, oB = ot * 64;

    int tid  = threadIdx.x;
    int lane = tid & 31, wid = tid >> 5;
    int warp_m = wid & 1, warp_n = wid >> 1;
    int grp = lane >> 2, qd = lane & 3;

    int arow = tid >> 1, ahalf = tid & 1;
    int bk2  = tid >> 3, bng = (tid & 7) << 3;

    float acc[2][4][4];
#pragma unroll
    for (int i = 0; i < 2; i++)
#pragma unroll
        for (int j = 0; j < 4; j++)
#pragma unroll
            for (int e = 0; e < 4; e++) acc[i][j][e] = 0.f;

    {
        const float4* aS = (const float4*)&Wm[(oB + arow) * C_ + ahalf * 16];
        const float4* b0S = (const float4*)&X[(2 * bk2    ) * N + nB + bng];
        const float4* b1S = (const float4*)&X[(2 * bk2 + 1) * N + nB + bng];
        uint32_t aw[8], bw[8];
#pragma unroll
        for (int g = 0; g < 4; g++) {
            float4 w = aS[g];
            aw[2 * g]     = pkbf(w.x, w.y);
            aw[2 * g + 1] = pkbf(w.z, w.w);
        }
#pragma unroll
        for (int g = 0; g < 2; g++) {
            float4 lo = b0S[g], hi = b1S[g];
            bw[4 * g + 0] = pkbf(lo.x, hi.x);
            bw[4 * g + 1] = pkbf(lo.y, hi.y);
            bw[4 * g + 2] = pkbf(lo.z, hi.z);
            bw[4 * g + 3] = pkbf(lo.w, hi.w);
        }
        *(uint4*)&sA[0][arow * 20 + ahalf * 8]     = *(uint4*)&aw[0];
        *(uint4*)&sA[0][arow * 20 + ahalf * 8 + 4] = *(uint4*)&aw[4];
        *(uint4*)&sB[0][bk2 * 68 + bng]            = *(uint4*)&bw[0];
        *(uint4*)&sB[0][bk2 * 68 + bng + 4]        = *(uint4*)&bw[4];
    }
    __syncthreads();

    int buf = 0;
    for (int cc = 0; cc < C_; cc += 32) {
        bool pf = cc + 32 < C_;
        float4 wreg[4], x0reg[2], x1reg[2];
        if (pf) {
            const float4* aS = (const float4*)&Wm[(oB + arow) * C_ + cc + 32 + ahalf * 16];
            const float4* b0S = (const float4*)&X[(cc + 32 + 2 * bk2    ) * N + nB + bng];
            const float4* b1S = (const float4*)&X[(cc + 32 + 2 * bk2 + 1) * N + nB + bng];
#pragma unroll
            for (int g = 0; g < 4; g++) wreg[g] = aS[g];
            x0reg[0] = b0S[0]; x0reg[1] = b0S[1];
            x1reg[0] = b1S[0]; x1reg[1] = b1S[1];
        }
        const uint32_t* cA = sA[buf];
        const uint32_t* cB = sB[buf];
#pragma unroll
        for (int ks = 0; ks < 2; ks++) {
            int kb = ks << 3;
            uint32_t afr[2][4];
#pragma unroll
            for (int ms = 0; ms < 2; ms++) {
                int base = warp_m * 32 + ms * 16 + grp;
                afr[ms][0] = cA[(base    ) * 20 + kb + qd];
                afr[ms][1] = cA[(base + 8) * 20 + kb + qd];
                afr[ms][2] = cA[(base    ) * 20 + kb + 4 + qd];
                afr[ms][3] = cA[(base + 8) * 20 + kb + 4 + qd];
            }
            uint32_t bfr[4][2];
#pragma unroll
            for (int ns = 0; ns < 4; ns++) {
                int n = warp_n * 32 + ns * 8 + grp;
                bfr[ns][0] = cB[(kb + qd    ) * 68 + n];
                bfr[ns][1] = cB[(kb + 4 + qd) * 68 + n];
            }
#pragma unroll
            for (int ms = 0; ms < 2; ms++)
#pragma unroll
                for (int ns = 0; ns < 4; ns++)
                    mma_bf16(acc[ms][ns], afr[ms], bfr[ns]);
        }
        if (pf) {
            uint32_t* nA = sA[buf ^ 1];
            uint32_t* nBp = sB[buf ^ 1];
            uint32_t aw[8], bw[8];
#pragma unroll
            for (int g = 0; g < 4; g++) {
                aw[2 * g]     = pkbf(wreg[g].x, wreg[g].y);
                aw[2 * g + 1] = pkbf(wreg[g].z, wreg[g].w);
            }
#pragma unroll
            for (int g = 0; g < 2; g++) {
                float4 lo = x0reg[g], hi = x1reg[g];
                bw[4 * g + 0] = pkbf(lo.x, hi.x);
                bw[4 * g + 1] = pkbf(lo.y, hi.y);
                bw[4 * g + 2] = pkbf(lo.z, hi.z);
                bw[4 * g + 3] = pkbf(lo.w, hi.w);
            }
            *(uint4*)&nA[arow * 20 + ahalf * 8]     = *(uint4*)&aw[0];
            *(uint4*)&nA[arow * 20 + ahalf * 8 + 4] = *(uint4*)&aw[4];
            *(uint4*)&nBp[bk2 * 68 + bng]           = *(uint4*)&bw[0];
            *(uint4*)&nBp[bk2 * 68 + bng + 4]       = *(uint4*)&bw[4];
        }
        __syncthreads();
        buf ^= 1;
    }

    if (!transp) {
#pragma unroll
        for (int ms = 0; ms < 2; ms++)
#pragma unroll
            for (int part = 0; part < 2; part++) {
                int row = warp_m * 32 + ms * 16 + grp + part * 8;
                float bv_ = bias[oB + row];
#pragma unroll
                for (int ns = 0; ns < 4; ns++) {
                    float2 val = make_float2(acc[ms][ns][2 * part] + bv_,
                                             acc[ms][ns][2 * part + 1] + bv_);
                    *(float2*)&Cout[(oB + row) * N + nB + warp_n * 32 + ns * 8 + 2 * qd] = val;
                }
            }
    } else {
        float* sT = (float*)smu;
        __syncthreads();
#pragma unroll
        for (int ms = 0; ms < 2; ms++)
#pragma unroll
            for (int part = 0; part < 2; part++) {
                int row = warp_m * 32 + ms * 16 + grp + part * 8;
                float bv_ = bias[oB + row];
#pragma unroll
                for (int ns = 0; ns < 4; ns++) {
                    int n = warp_n * 32 + ns * 8 + 2 * qd;
                    sT[(n    ) * 65 + row] = acc[ms][ns][2 * part] + bv_;
                    sT[(n + 1) * 65 + row] = acc[ms][ns][2 * part + 1] + bv_;
                }
            }
        __syncthreads();
#pragma unroll
        for (int it = 0; it < 32; it++) {
            int idx = it * 128 + tid;
            int n = idx >> 6, o = idx & 63;
            Cout[(nB + n) * C_ + oB + o] = sT[n * 65 + o];
        }
    }
}

// ---------------------------------------------------------------------------
// Kernel 3: fused attention via mma.sync tf32, 16-QUERY TILES.
// Grid (36, 8) = 288 CTAs x 256 thr; smem 98.3KB -> 2 CTAs/SM.
// M=16 = one m16n8k8 A-fragment per mma; pass-2 A-frag LDS halves.
// Staging / double-buffering / softmax structure = R8-proven.
// ---------------------------------------------------------------------------
__global__ void __launch_bounds__(256) attn_kernel(const float* __restrict__ x,
                            const float* __restrict__ gamma_p,
                            float* __restrict__ out) {
    extern __shared__ float smd[];
    uint32_t* sQf = (uint32_t*)smd;        // 1024: A-frags [ks 8][lane 32][4]
    float* sKV0 = smd + 1024;              // 64*68 = 4352 (tf32 bits)
    float* sKV1 = sKV0 + 4352;             // 4352
    float* sE   = sKV1 + 4352;             // 16*964 = 15424
    float* sInv = sE + QT_ * SEW;          // 16
    // total 25168 floats = 100672 B

    int h   = blockIdx.y;
    int q0  = blockIdx.x * QT_;
    int tid = threadIdx.x;
    int w = tid >> 5, lane = tid & 31, grp = lane >> 2, qd = lane & 3;
    int dstg = tid >> 2, cstg = (tid & 3) << 4;
    float* sKVb[2] = { sKV0, sKV1 };

    // ---- Stage Q fragments (one-time): (q,d) -> [ks][lane][reg] ----
    {
        int q = tid >> 4, db = (tid & 15) << 2;
        float4 q4 = *(const float4*)&g_QT[(q0 + q) * C_ + h * HD + db];
        float qv[4] = {q4.x, q4.y, q4.z, q4.w};
#pragma unroll
        for (int e = 0; e < 4; e++) {
            int d = db + e;
            int lidx = ((d >> 3) * 32 + (q & 7) * 4 + (d & 3)) * 4
                     + (q >> 3) + (((d >> 2) & 1) << 1);
            sQf[lidx] = f2tf(qv[e]);
        }
    }
    // ---- preload K chunk 0: sK[key][68] ----
    {
        const float4* src = (const float4*)&g_KT[dstg * C_ + h * HD + cstg];
        uint32_t* dst = (uint32_t*)&sKV0[dstg * 68 + cstg];
#pragma unroll
        for (int j = 0; j < 4; j++) {
            float4 r = src[j];
            *(uint4*)&dst[4 * j] = make_uint4(f2tf(r.x), f2tf(r.y), f2tf(r.z), f2tf(r.w));
        }
    }
    __syncthreads();

    // ---- Pass 1: E = Q^T K (M=16, one A-frag per mma) ----
    for (int kc = 0, c = 0; kc < KP; kc += 64, c++) {
        const uint32_t* cK = (const uint32_t*)sKVb[c & 1];
        bool pf = kc + 64 < KP;
        float4 r0, r1, r2, r3;
        if (pf) {
            const float4* src = (const float4*)&g_KT[(kc + 64 + dstg) * C_ + h * HD + cstg];
            r0 = src[0]; r1 = src[1]; r2 = src[2]; r3 = src[3];
        }
        float acc[4] = {0.f, 0.f, 0.f, 0.f};
#pragma unroll
        for (int ks = 0; ks < 8; ks++) {
            uint4 a = *(const uint4*)&sQf[(ks * 32 + lane) * 4];
            uint32_t bf[2];
            bf[0] = cK[(w * 8 + grp) * 68 + ks * 8 + qd];
            bf[1] = cK[(w * 8 + grp) * 68 + ks * 8 + 4 + qd];
            mma_tf32(acc, (const uint32_t*)&a, bf);
        }
        {
            int col = kc + w * 8 + 2 * qd;
            *(float2*)&sE[(grp    ) * SEW + col] = make_float2(acc[0], acc[1]);
            *(float2*)&sE[(grp + 8) * SEW + col] = make_float2(acc[2], acc[3]);
        }
        if (pf) {
            uint32_t* dst = (uint32_t*)&sKVb[(c & 1) ^ 1][dstg * 68 + cstg];
            *(uint4*)&dst[0]  = make_uint4(f2tf(r0.x), f2tf(r0.y), f2tf(r0.z), f2tf(r0.w));
            *(uint4*)&dst[4]  = make_uint4(f2tf(r1.x), f2tf(r1.y), f2tf(r1.z), f2tf(r1.w));
            *(uint4*)&dst[8]  = make_uint4(f2tf(r2.x), f2tf(r2.y), f2tf(r2.z), f2tf(r2.w));
            *(uint4*)&dst[12] = make_uint4(f2tf(r3.x), f2tf(r3.y), f2tf(r3.z), f2tf(r3.w));
        }
        __syncthreads();
    }

    // ---- prefetch V chunk 0 (sV[d][key]) ----
    float4 v0r, v1r, v2r, v3r;
    {
        const float4* src = (const float4*)&g_V[(h * HD + dstg) * KP + cstg];
        v0r = src[0]; v1r = src[1]; v2r = src[2]; v3r = src[3];
    }

    // ---- Multiplicity-weighted softmax; tf32-rounded P in place ----
    {
        int row = tid >> 4, part = tid & 15;     // 16 threads per query row
        float* Er = &sE[row * SEW];
        int i0 = part * 60;
        float m = -1e30f;
        for (int i = i0; i < i0 + 60; i++) m = fmaxf(m, Er[i]);
        m = fmaxf(m, __shfl_xor_sync(~0u, m, 1));
        m = fmaxf(m, __shfl_xor_sync(~0u, m, 2));
        m = fmaxf(m, __shfl_xor_sync(~0u, m, 4));
        m = fmaxf(m, __shfl_xor_sync(~0u, m, 8));
        float s = 0.f;
        for (int i = i0; i < i0 + 60; i++) {
            float wgt = 0.f;
            if (i < PP) {
                int pr = i / PW, pc = i - pr * PW;
                int mr = min(pr + 1, min(7, PW - pr));
                int mc = min(pc + 1, min(7, PW - pc));
                wgt = (float)(mr * mc);
            }
            float p = __uint_as_float(f2tf(wgt * __expf(Er[i] - m)));
            Er[i] = p;
            s += p;
        }
        s += __shfl_xor_sync(~0u, s, 1);
        s += __shfl_xor_sync(~0u, s, 2);
        s += __shfl_xor_sync(~0u, s, 4);
        s += __shfl_xor_sync(~0u, s, 8);
        if (part == 0) sInv[row] = 1.f / s;
    }
    {
        uint32_t* dst = (uint32_t*)&sKV0[dstg * 68 + cstg];
        *(uint4*)&dst[0]  = make_uint4(f2tf(v0r.x), f2tf(v0r.y), f2tf(v0r.z), f2tf(v0r.w));
        *(uint4*)&dst[4]  = make_uint4(f2tf(v1r.x), f2tf(v1r.y), f2tf(v1r.z), f2tf(v1r.w));
        *(uint4*)&dst[8]  = make_uint4(f2tf(v2r.x), f2tf(v2r.y), f2tf(v2r.z), f2tf(v2r.w));
        *(uint4*)&dst[12] = make_uint4(f2tf(v3r.x), f2tf(v3r.y), f2tf(v3r.z), f2tf(v3r.w));
    }
    __syncthreads();

    // ---- Pass 2: out = P V (M=16, 4 scalar A-frag LDS per mma) ----
    float o[4] = {0.f, 0.f, 0.f, 0.f};
    for (int kc = 0, c = 0; kc < KP; kc += 64, c++) {
        const uint32_t* cV = (const uint32_t*)sKVb[c & 1];
        bool pf = kc + 64 < KP;
        float4 r0, r1, r2, r3;
        if (pf) {
            const float4* src = (const float4*)&g_V[(h * HD + dstg) * KP + kc + 64 + cstg];
            r0 = src[0]; r1 = src[1]; r2 = src[2]; r3 = src[3];
        }
#pragma unroll
        for (int ks = 0; ks < 8; ks++) {
            int colb = kc + ks * 8;
            uint32_t a[4], bf[2];
            a[0] = __float_as_uint(sE[(grp    ) * SEW + colb + qd]);
            a[1] = __float_as_uint(sE[(grp + 8) * SEW + colb + qd]);
            a[2] = __float_as_uint(sE[(grp    ) * SEW + colb + 4 + qd]);
            a[3] = __float_as_uint(sE[(grp + 8) * SEW + colb + 4 + qd]);
            bf[0] = cV[(w * 8 + grp) * 68 + ks * 8 + qd];
            bf[1] = cV[(w * 8 + grp) * 68 + ks * 8 + 4 + qd];
            mma_tf32(o, a, bf);
        }
        if (pf) {
            uint32_t* dst = (uint32_t*)&sKVb[(c & 1) ^ 1][dstg * 68 + cstg];
            *(uint4*)&dst[0]  = make_uint4(f2tf(r0.x), f2tf(r0.y), f2tf(r0.z), f2tf(r0.w));
            *(uint4*)&dst[4]  = make_uint4(f2tf(r1.x), f2tf(r1.y), f2tf(r1.z), f2tf(r1.w));
            *(uint4*)&dst[8]  = make_uint4(f2tf(r2.x), f2tf(r2.y), f2tf(r2.z), f2tf(r2.w));
            *(uint4*)&dst[12] = make_uint4(f2tf(r3.x), f2tf(r3.y), f2tf(r3.z), f2tf(r3.w));
        }
        __syncthreads();
    }

    // ---- Epilogue via smem transpose: out = gamma*acc/denom + x ----
    {
        float* sT = sKV0;                        // [d][q] 64 x 17 = 1088
        int dc = w * 8 + 2 * qd;
        sT[(dc    ) * 17 + grp    ] = o[0];
        sT[(dc + 1) * 17 + grp    ] = o[1];
        sT[(dc    ) * 17 + grp + 8] = o[2];
        sT[(dc + 1) * 17 + grp + 8] = o[3];
        __syncthreads();
        float g = *gamma_p;
#pragma unroll
        for (int it = 0; it < 4; it++) {
            int i = it * 256 + tid;
            int d = i >> 4, q = i & 15;
            int gi = (h * HD + d) * HW + q0 + q;
            out[gi] = g * sT[d * 17 + q] * sInv[q] + x[gi];
        }
    }
}

// ---------------------------------------------------------------------------
extern "C" void kernel_launch(void* const* d_in, const int* in_sizes, int n_in,
                              void* d_out, int out_size) {
    const float* x     = (const float*)d_in[0];
    const float* Wq    = (const float*)d_in[1];
    const float* bq    = (const float*)d_in[2];
    const float* Wk    = (const float*)d_in[3];
    const float* bk    = (const float*)d_in[4];
    const float* Wv    = (const float*)d_in[5];
    const float* bv    = (const float*)d_in[6];
    const float* gamma = (const float*)d_in[7];
    float* out = (float*)d_out;

    pad_kernel<<<(C_ * KP + 255) / 256, 256>>>(x);
    gemm_all_kernel<<<312, 128>>>(Wq, bq, Wk, bk, Wv, bv, x);

    const int attn_smem = (1024 + 2 * 4352 + QT_ * SEW + 16) * 4;  // 100672
    cudaFuncSetAttribute(attn_kernel, cudaFuncAttributeMaxDynamicSharedMemorySize, attn_smem);
    attn_kernel<<<dim3(HW / QT_, NH), 256, attn_smem>>>(x, gamma, out);
}